// round 13
// baseline (speedup 1.0000x reference)
#include <cuda_runtime.h>
#include <cuda_bf16.h>
#include <cstdint>

#define NB    16
#define PP    1024
#define KNB   16
#define DIMS  3
#define C_IN  128
#define C_MID 64
#define C_OUT 256
#define DMUL  2
#define C_CAT 192
#define NPTS  (NB*PP)        // 16384
#define KKDIM 256            // K*K
#define EPSV  1e-5f

// ---------------- scratch ----------------
__device__ float g_lift[NPTS*KNB*C_MID];
__device__ float g_X0[NPTS*KKDIM];
__device__ float g_X1[NPTS*KKDIM];
__device__ float g_X2[NPTS*KKDIM];
__device__ float g_dw[NPTS*C_CAT*DMUL];
__device__ float g_wt1[KKDIM*KKDIM];         // x1_w transposed [N,K]
__device__ float g_wt2[KKDIM*KKDIM];
__device__ float g_wtd[C_MID*C_MID];         // d2_w transposed
__device__ double g_sum[C_OUT];
__device__ double g_sumsq[C_OUT];
__device__ float g_scale[C_OUT];
__device__ float g_shift[C_OUT];

// ---------------- K0 ----------------
__global__ void k_zero() {
    int t = threadIdx.x;
    if (t < C_OUT) { g_sum[t] = 0.0; g_sumsq[t] = 0.0; }
}

// ---------------- transpose: src[R][C] -> dst[C][R] ----------------
__global__ void k_transp(const float* __restrict__ src, float* __restrict__ dst,
                         int R, int C) {
    __shared__ float s[32][33];
    int bx = blockIdx.x, by = blockIdx.y;
    int tx = threadIdx.x & 31, ty = threadIdx.x >> 5;
    #pragma unroll
    for (int i = 0; i < 4; ++i) {
        int r = by * 32 + ty + i * 8;
        s[ty + i * 8][tx] = src[r * C + bx * 32 + tx];
    }
    __syncthreads();
    #pragma unroll
    for (int i = 0; i < 4; ++i) {
        int r = bx * 32 + ty + i * 8;
        dst[r * R + by * 32 + tx] = s[tx][ty + i * 8];
    }
}

__device__ __forceinline__ void mma16816(float* c, const uint32_t* a,
                                         uint32_t b0, uint32_t b1) {
    asm volatile(
        "mma.sync.aligned.m16n8k16.row.col.f32.bf16.bf16.f32 "
        "{%0,%1,%2,%3}, {%4,%5,%6,%7}, {%8,%9}, {%0,%1,%2,%3};"
        : "+f"(c[0]), "+f"(c[1]), "+f"(c[2]), "+f"(c[3])
        : "r"(a[0]), "r"(a[1]), "r"(a[2]), "r"(a[3]), "r"(b0), "r"(b1));
}

__device__ __forceinline__ void ldsm_x4(uint32_t& r0, uint32_t& r1,
                                        uint32_t& r2, uint32_t& r3, uint32_t addr) {
    asm volatile("ldmatrix.sync.aligned.m8n8.x4.shared.b16 {%0,%1,%2,%3}, [%4];"
                 : "=r"(r0), "=r"(r1), "=r"(r2), "=r"(r3) : "r"(addr));
}
__device__ __forceinline__ uint32_t smem_u32(const void* p) {
    return (uint32_t)__cvta_generic_to_shared(p);
}

__device__ __forceinline__ void split_bf16(float4 v, __nv_bfloat162& h01,
                                           __nv_bfloat162& h23,
                                           __nv_bfloat162& l01,
                                           __nv_bfloat162& l23) {
    h01 = __float22bfloat162_rn(make_float2(v.x, v.y));
    h23 = __float22bfloat162_rn(make_float2(v.z, v.w));
    float2 f01 = __bfloat1622float2(h01);
    float2 f23 = __bfloat1622float2(h23);
    l01 = __float22bfloat162_rn(make_float2(v.x - f01.x, v.y - f01.y));
    l23 = __float22bfloat162_rn(make_float2(v.z - f23.x, v.w - f23.y));
}

// ---------------- K1 fused: pts_local -> d1 MLP -> d2 MMA -> g_lift, + X0 ----------------
// 1 CTA = 8 points = 128 rows (one MMA tile). d2 GEMM done in-place via bf16x3 mma.
#define PB1 8
#define PSTR 72   // smem col stride (bf16 elems); 144 B rows: 16B-aligned, conflict-free
#define SPL_BYTES 1536                      // PB1*KNB*DIMS floats = 384*4
__global__ __launch_bounds__(256) void k_prep(
        const float* __restrict__ rep_pt, const float* __restrict__ pts,
        const float* __restrict__ d1_w, const float* __restrict__ d1_b,
        const float* __restrict__ d2wt, const float* __restrict__ d2_b,
        const float* __restrict__ cv_w, const float* __restrict__ cv_b) {
    extern __shared__ char smem[];
    float* s_pl = (float*)smem;                                        // 1536 B
    __nv_bfloat16* sA = (__nv_bfloat16*)(smem + SPL_BYTES);            // [2][128][PSTR]
    __nv_bfloat16* sB = (__nv_bfloat16*)(smem + SPL_BYTES + 2*128*PSTR*2); // [2][64][PSTR]
#define SA(pl, r, cc) sA[((pl)*128 + (r))*PSTR + (cc)]
#define SB(pl, r, cc) sB[((pl)*64 + (r))*PSTR + (cc)]

    const int t = threadIdx.x;
    const int pbase = blockIdx.x * PB1;
    const int wid = t >> 5, lid = t & 31;
    const int g = lid >> 2, tg = lid & 3;
    const int wm = wid & 3, wn = wid >> 2;

    for (int idx = t; idx < PB1*KNB*DIMS; idx += 256) {
        int p = idx / (KNB*DIMS);
        int rem = idx % (KNB*DIMS);
        int k = rem / DIMS, d = rem % DIMS;
        int gp = pbase + p;
        s_pl[idx] = pts[(gp*KNB + k)*DIMS + d] - rep_pt[gp*DIMS + d];
    }
    // stage d2wt [64][64] as bf16 hi/lo
    for (int idx = t * 4; idx < C_MID*C_MID; idx += 1024) {
        int row = idx >> 6, col = idx & 63;
        float4 v = *reinterpret_cast<const float4*>(&d2wt[idx]);
        __nv_bfloat162 h01, h23, l01, l23;
        split_bf16(v, h01, h23, l01, l23);
        *reinterpret_cast<__nv_bfloat162*>(&SB(0, row, col))     = h01;
        *reinterpret_cast<__nv_bfloat162*>(&SB(0, row, col + 2)) = h23;
        *reinterpret_cast<__nv_bfloat162*>(&SB(1, row, col))     = l01;
        *reinterpret_cast<__nv_bfloat162*>(&SB(1, row, col + 2)) = l23;
    }
    __syncthreads();

    // h = relu(pts_local @ d1_w + d1_b) -> sA hi/lo (2 cols x 16 rows per thread)
    {
        int c0 = (t & 31) * 2;
        int rg = t >> 5;                           // 0..7, 16 rows each
        float w00 = d1_w[0*C_MID + c0], w01 = d1_w[0*C_MID + c0 + 1];
        float w10 = d1_w[1*C_MID + c0], w11 = d1_w[1*C_MID + c0 + 1];
        float w20 = d1_w[2*C_MID + c0], w21 = d1_w[2*C_MID + c0 + 1];
        float b0 = d1_b[c0], b1 = d1_b[c0 + 1];
        #pragma unroll
        for (int r = 0; r < 16; ++r) {
            int row = rg * 16 + r;
            const float* pl = &s_pl[row * DIMS];
            float v0 = fmaxf(b0 + pl[0]*w00 + pl[1]*w10 + pl[2]*w20, 0.f);
            float v1 = fmaxf(b1 + pl[0]*w01 + pl[1]*w11 + pl[2]*w21, 0.f);
            __nv_bfloat162 h = __float22bfloat162_rn(make_float2(v0, v1));
            float2 hf = __bfloat1622float2(h);
            __nv_bfloat162 l = __float22bfloat162_rn(make_float2(v0 - hf.x, v1 - hf.y));
            *reinterpret_cast<__nv_bfloat162*>(&SA(0, row, c0)) = h;
            *reinterpret_cast<__nv_bfloat162*>(&SA(1, row, c0)) = l;
        }
    }
    __syncthreads();

    // d2 MMA: 128x64, K=64, bf16x3.  8 warps = 4m x 2n; warp tile 32 x 32.  ldmatrix frags.
    {
        float acc[2][4][4];
        #pragma unroll
        for (int mt = 0; mt < 2; ++mt)
            #pragma unroll
            for (int nt = 0; nt < 4; ++nt)
                #pragma unroll
                for (int i = 0; i < 4; ++i) acc[mt][nt][i] = 0.f;

        const int arow = ((lid >> 3) & 1) * 8 + (lid & 7);   // + mt*16 + wm*32
        const int acol = (lid >> 4) * 8;                      // + kb0
        const int brow = (lid >> 4) * 8 + (lid & 7);          // + nt*8 + wn*32
        const int bcol = ((lid >> 3) & 1) * 8;                // + kb0

        #pragma unroll
        for (int ks = 0; ks < 4; ++ks) {
            int kb0 = ks * 16;
            uint32_t ah[2][4], al[2][4];
            #pragma unroll
            for (int mt = 0; mt < 2; ++mt) {
                int r = wm * 32 + mt * 16 + arow;
                ldsm_x4(ah[mt][0], ah[mt][1], ah[mt][2], ah[mt][3],
                        smem_u32(&SA(0, r, kb0 + acol)));
                ldsm_x4(al[mt][0], al[mt][1], al[mt][2], al[mt][3],
                        smem_u32(&SA(1, r, kb0 + acol)));
            }
            #pragma unroll
            for (int ntp = 0; ntp < 2; ++ntp) {
                int nt = ntp * 2;
                int n = wn * 32 + nt * 8 + brow;
                uint32_t bh0, bh1, bh2, bh3, bl0, bl1, bl2, bl3;
                ldsm_x4(bh0, bh1, bh2, bh3, smem_u32(&SB(0, n, kb0 + bcol)));
                ldsm_x4(bl0, bl1, bl2, bl3, smem_u32(&SB(1, n, kb0 + bcol)));
                #pragma unroll
                for (int mt = 0; mt < 2; ++mt) {
                    mma16816(acc[mt][nt],     ah[mt], bh0, bh1);
                    mma16816(acc[mt][nt],     ah[mt], bl0, bl1);
                    mma16816(acc[mt][nt],     al[mt], bh0, bh1);
                    mma16816(acc[mt][nt + 1], ah[mt], bh2, bh3);
                    mma16816(acc[mt][nt + 1], ah[mt], bl2, bl3);
                    mma16816(acc[mt][nt + 1], al[mt], bh2, bh3);
                }
            }
        }
        // epilogue: relu(acc + d2_b) -> g_lift
        #pragma unroll
        for (int mt = 0; mt < 2; ++mt) {
            int row0 = wm * 32 + mt * 16 + g;
            #pragma unroll
            for (int nt = 0; nt < 4; ++nt) {
                int col = wn * 32 + nt * 8 + 2 * tg;
                float b0 = d2_b[col], b1 = d2_b[col + 1];
                float v0 = fmaxf(acc[mt][nt][0] + b0, 0.f);
                float v1 = fmaxf(acc[mt][nt][1] + b1, 0.f);
                float v2 = fmaxf(acc[mt][nt][2] + b0, 0.f);
                float v3 = fmaxf(acc[mt][nt][3] + b1, 0.f);
                *reinterpret_cast<float2*>(
                    &g_lift[(size_t)(pbase*KNB + row0)*C_MID + col]) = make_float2(v0, v1);
                *reinterpret_cast<float2*>(
                    &g_lift[(size_t)(pbase*KNB + row0 + 8)*C_MID + col]) = make_float2(v2, v3);
            }
        }
    }

    // X0 = relu(einsum('pkd,odk->po') + cv_b)  (reads only s_pl)
    {
        int o = t;
        float acc[PB1];
        float b = cv_b[o];
        #pragma unroll
        for (int p = 0; p < PB1; ++p) acc[p] = b;
        #pragma unroll
        for (int d = 0; d < DIMS; ++d)
            for (int k = 0; k < KNB; ++k) {
                float w = cv_w[o*(DIMS*KNB) + d*KNB + k];
                #pragma unroll
                for (int p = 0; p < PB1; ++p)
                    acc[p] += s_pl[(p*KNB + k)*DIMS + d] * w;
            }
        #pragma unroll
        for (int p = 0; p < PB1; ++p)
            g_X0[(size_t)(pbase + p)*KKDIM + o] = fmaxf(acc[p], 0.f);
    }
#undef SA
#undef SB
}

// ---------------- bf16x3 tensor-core GEMM v3: ldmatrix + double-buffered smem ----------------
// C[M, Nn] = act(A[M, KD] @ Bt[Nn, KD]^T (+bias)).  Block tile 128x128, BK=32.
#define SPAD 40                               // 80 B rows
#define PLANE (128 * SPAD)                    // elems per plane
#define STAGE (4 * PLANE)                     // Ah, Al, Bh, Bl
template<int KD, bool RELU, bool USE_BIAS>
__global__ __launch_bounds__(256) void k_mma(
        const float* __restrict__ A, const float* __restrict__ Bt,
        const float* __restrict__ bias, float* __restrict__ C, int Nn) {
    extern __shared__ char smem_raw[];
    __nv_bfloat16* smem = (__nv_bfloat16*)smem_raw;
    constexpr int KCH = KD / 32;

    const int t = threadIdx.x;
    const int wid = t >> 5, lid = t & 31;
    const int g = lid >> 2, tg = lid & 3;
    const int wm = wid & 3, wn = wid >> 2;
    const long rowBase = (long)blockIdx.y * 128;
    const int nBase = blockIdx.x * 128;

    const int ldrow = t >> 3, ldcol = (t & 7) * 4;   // 256 thr: 32 rows x 8 col-groups
    const int arow = ((lid >> 3) & 1) * 8 + (lid & 7);
    const int acol = (lid >> 4) * 8;
    const int brow = (lid >> 4) * 8 + (lid & 7);
    const int bcol = ((lid >> 3) & 1) * 8;

    float acc[2][8][4];
    #pragma unroll
    for (int mt = 0; mt < 2; ++mt)
        #pragma unroll
        for (int nt = 0; nt < 8; ++nt)
            #pragma unroll
            for (int i = 0; i < 4; ++i) acc[mt][nt][i] = 0.f;

    auto load_stage = [&](int ch, int st) {
        __nv_bfloat16* sAh = smem + st * STAGE;
        __nv_bfloat16* sAl = sAh + PLANE;
        __nv_bfloat16* sBh = sAh + 2 * PLANE;
        __nv_bfloat16* sBl = sAh + 3 * PLANE;
        #pragma unroll
        for (int i = 0; i < 4; ++i) {           // 128 rows x 32 cols, 4 passes
            int row = ldrow + i * 32;
            int col = ldcol;
            float4 va = *reinterpret_cast<const float4*>(
                &A[(rowBase + row) * KD + ch * 32 + col]);
            float4 vb = *reinterpret_cast<const float4*>(
                &Bt[(long)(nBase + row) * KD + ch * 32 + col]);
            __nv_bfloat162 h01, h23, l01, l23;
            split_bf16(va, h01, h23, l01, l23);
            int off = row * SPAD + col;
            *reinterpret_cast<__nv_bfloat162*>(&sAh[off])     = h01;
            *reinterpret_cast<__nv_bfloat162*>(&sAh[off + 2]) = h23;
            *reinterpret_cast<__nv_bfloat162*>(&sAl[off])     = l01;
            *reinterpret_cast<__nv_bfloat162*>(&sAl[off + 2]) = l23;
            split_bf16(vb, h01, h23, l01, l23);
            *reinterpret_cast<__nv_bfloat162*>(&sBh[off])     = h01;
            *reinterpret_cast<__nv_bfloat162*>(&sBh[off + 2]) = h23;
            *reinterpret_cast<__nv_bfloat162*>(&sBl[off])     = l01;
            *reinterpret_cast<__nv_bfloat162*>(&sBl[off + 2]) = l23;
        }
    };

    load_stage(0, 0);
    __syncthreads();

    for (int ch = 0; ch < KCH; ++ch) {
        int p = ch & 1;
        if (ch + 1 < KCH) load_stage(ch + 1, p ^ 1);

        __nv_bfloat16* sAh = smem + p * STAGE;
        __nv_bfloat16* sAl = sAh + PLANE;
        __nv_bfloat16* sBh = sAh + 2 * PLANE;
        __nv_bfloat16* sBl = sAh + 3 * PLANE;

        #pragma unroll
        for (int ks = 0; ks < 2; ++ks) {
            int kb0 = ks * 16;
            uint32_t ah[2][4], al[2][4];
            #pragma unroll
            for (int mt = 0; mt < 2; ++mt) {
                int r = wm * 32 + mt * 16 + arow;
                ldsm_x4(ah[mt][0], ah[mt][1], ah[mt][2], ah[mt][3],
                        smem_u32(&sAh[r * SPAD + kb0 + acol]));
                ldsm_x4(al[mt][0], al[mt][1], al[mt][2], al[mt][3],
                        smem_u32(&sAl[r * SPAD + kb0 + acol]));
            }
            #pragma unroll
            for (int ntp = 0; ntp < 4; ++ntp) {
                int nt = ntp * 2;
                int n = wn * 64 + nt * 8 + brow;
                uint32_t bh0, bh1, bh2, bh3, bl0, bl1, bl2, bl3;
                ldsm_x4(bh0, bh1, bh2, bh3, smem_u32(&sBh[n * SPAD + kb0 + bcol]));
                ldsm_x4(bl0, bl1, bl2, bl3, smem_u32(&sBl[n * SPAD + kb0 + bcol]));
                #pragma unroll
                for (int mt = 0; mt < 2; ++mt) {
                    mma16816(acc[mt][nt],     ah[mt], bh0, bh1);
                    mma16816(acc[mt][nt],     ah[mt], bl0, bl1);
                    mma16816(acc[mt][nt],     al[mt], bh0, bh1);
                    mma16816(acc[mt][nt + 1], ah[mt], bh2, bh3);
                    mma16816(acc[mt][nt + 1], ah[mt], bl2, bl3);
                    mma16816(acc[mt][nt + 1], al[mt], bh2, bh3);
                }
            }
        }
        __syncthreads();
    }

    #pragma unroll
    for (int mt = 0; mt < 2; ++mt) {
        long row0 = rowBase + wm * 32 + mt * 16 + g;
        #pragma unroll
        for (int nt = 0; nt < 8; ++nt) {
            int col = nBase + wn * 64 + nt * 8 + 2 * tg;
            float b0 = USE_BIAS ? bias[col]     : 0.f;
            float b1 = USE_BIAS ? bias[col + 1] : 0.f;
            float v0 = acc[mt][nt][0] + b0, v1 = acc[mt][nt][1] + b1;
            float v2 = acc[mt][nt][2] + b0, v3 = acc[mt][nt][3] + b1;
            if (RELU) {
                v0 = fmaxf(v0, 0.f); v1 = fmaxf(v1, 0.f);
                v2 = fmaxf(v2, 0.f); v3 = fmaxf(v3, 0.f);
            }
            *reinterpret_cast<float2*>(&C[row0 * Nn + col])       = make_float2(v0, v1);
            *reinterpret_cast<float2*>(&C[(row0 + 8) * Nn + col]) = make_float2(v2, v3);
        }
    }
}

// ---------------- K4: fts_X = X @ [lifted|fts], then depthwise conv -> g_dw ----------------
#define PB4 8
__global__ __launch_bounds__(192) void k_xform(
        const float* __restrict__ fts,
        const float* __restrict__ dw_w, const float* __restrict__ dw_b) {
    __shared__ __align__(16) float s_Xt[16][20];   // transposed X, padded rows
    const int t = threadIdx.x;                     // 0..191 = channel c
    const int pbase = blockIdx.x * PB4;
    const int c = t;
    float wreg[DMUL][KNB];
    float breg[DMUL];
    #pragma unroll
    for (int m = 0; m < DMUL; ++m) {
        int jj = c*DMUL + m;
        breg[m] = dw_b[jj];
        #pragma unroll
        for (int k = 0; k < KNB; ++k) wreg[m][k] = dw_w[jj*KNB + k];
    }
    for (int p = 0; p < PB4; ++p) {
        int gp = pbase + p;
        for (int idx = t; idx < KKDIM; idx += 192)     // s_Xt[j][k] = X[k][j]
            s_Xt[idx & 15][idx >> 4] = g_X2[(size_t)gp*KKDIM + idx];
        __syncthreads();
        float fX[KNB];
        #pragma unroll
        for (int k = 0; k < KNB; ++k) fX[k] = 0.f;
        #pragma unroll 4
        for (int j = 0; j < KNB; ++j) {
            float catv = (c < C_MID) ? g_lift[(size_t)(gp*KNB + j)*C_MID + c]
                                     : fts[(size_t)(gp*KNB + j)*C_IN + (c - C_MID)];
            #pragma unroll
            for (int q = 0; q < 4; ++q) {
                float4 xv = *reinterpret_cast<const float4*>(&s_Xt[j][q * 4]);
                fX[q*4+0] += xv.x * catv;
                fX[q*4+1] += xv.y * catv;
                fX[q*4+2] += xv.z * catv;
                fX[q*4+3] += xv.w * catv;
            }
        }
        #pragma unroll
        for (int m = 0; m < DMUL; ++m) {
            float acc = breg[m];
            #pragma unroll
            for (int k = 0; k < KNB; ++k)
                acc += fX[k] * wreg[m][k];
            g_dw[(size_t)gp*(C_CAT*DMUL) + c*DMUL + m] = acc;
        }
        __syncthreads();
    }
}

// ---------------- K5: per-channel sum / sumsq ----------------
__global__ void k_stats(const float* __restrict__ out) {
    const int c = threadIdx.x;
    const int rows_per = NPTS / gridDim.x;
    const int r0 = blockIdx.x * rows_per;
    double s = 0.0, s2 = 0.0;
    for (int r = 0; r < rows_per; ++r) {
        float v = out[(size_t)(r0 + r)*C_OUT + c];
        s += v; s2 += (double)v * v;
    }
    atomicAdd(&g_sum[c], s);
    atomicAdd(&g_sumsq[c], s2);
}

// ---------------- K5b ----------------
__global__ void k_finstats(const float* __restrict__ bn_g, const float* __restrict__ bn_b) {
    int c = threadIdx.x;
    double inv = 1.0 / (double)NPTS;
    double mean = g_sum[c] * inv;
    double var  = g_sumsq[c] * inv - mean*mean;
    float sc = bn_g[c] * rsqrtf((float)var + EPSV);
    g_scale[c] = sc;
    g_shift[c] = bn_b[c] - (float)mean * sc;
}

// ---------------- K6: apply BN (float4) ----------------
__global__ void k_bn(float* __restrict__ out) {
    int idx = (blockIdx.x * 256 + threadIdx.x) * 4;
    int c = idx & (C_OUT - 1);
    float4 v = *reinterpret_cast<float4*>(&out[idx]);
    v.x = v.x * g_scale[c]   + g_shift[c];
    v.y = v.y * g_scale[c+1] + g_shift[c+1];
    v.z = v.z * g_scale[c+2] + g_shift[c+2];
    v.w = v.w * g_scale[c+3] + g_shift[c+3];
    *reinterpret_cast<float4*>(&out[idx]) = v;
}

// ---------------- launch ----------------
extern "C" void kernel_launch(void* const* d_in, const int* in_sizes, int n_in,
                              void* d_out, int out_size) {
    const float* rep_pt = (const float*)d_in[0];
    const float* pts    = (const float*)d_in[1];
    const float* fts    = (const float*)d_in[2];
    const float* d1_w   = (const float*)d_in[3];
    const float* d1_b   = (const float*)d_in[4];
    const float* d2_w   = (const float*)d_in[5];
    const float* d2_b   = (const float*)d_in[6];
    const float* cv_w   = (const float*)d_in[7];
    const float* cv_b   = (const float*)d_in[8];
    const float* x1_w   = (const float*)d_in[9];
    const float* x1_b   = (const float*)d_in[10];
    const float* x2_w   = (const float*)d_in[11];
    const float* x2_b   = (const float*)d_in[12];
    const float* dw_w   = (const float*)d_in[13];
    const float* dw_b   = (const float*)d_in[14];
    const float* pw_w   = (const float*)d_in[15];
    const float* bn_g   = (const float*)d_in[16];
    const float* bn_b   = (const float*)d_in[17];
    float* out = (float*)d_out;

    void *pX0, *pX1, *pX2, *pdw, *pwt1, *pwt2, *pwtd;
    cudaGetSymbolAddress(&pX0,  g_X0);
    cudaGetSymbolAddress(&pX1,  g_X1);
    cudaGetSymbolAddress(&pX2,  g_X2);
    cudaGetSymbolAddress(&pdw,  g_dw);
    cudaGetSymbolAddress(&pwt1, g_wt1);
    cudaGetSymbolAddress(&pwt2, g_wt2);
    cudaGetSymbolAddress(&pwtd, g_wtd);

    constexpr int PREP_SMEM = SPL_BYTES + 2*128*PSTR*2 + 2*64*PSTR*2;  // 56832
    constexpr int MMA_SMEM  = 2 * STAGE * 2;                            // 81920 B
    cudaFuncSetAttribute(k_prep, cudaFuncAttributeMaxDynamicSharedMemorySize, PREP_SMEM);
    cudaFuncSetAttribute(k_mma<256, true,  true >,
                         cudaFuncAttributeMaxDynamicSharedMemorySize, MMA_SMEM);
    cudaFuncSetAttribute(k_mma<256, false, true >,
                         cudaFuncAttributeMaxDynamicSharedMemorySize, MMA_SMEM);
    cudaFuncSetAttribute(k_mma<384, true,  false>,
                         cudaFuncAttributeMaxDynamicSharedMemorySize, MMA_SMEM);

    k_zero<<<1, 256>>>();
    k_transp<<<dim3(KKDIM/32, KKDIM/32), 256>>>(x1_w, (float*)pwt1, KKDIM, KKDIM);
    k_transp<<<dim3(KKDIM/32, KKDIM/32), 256>>>(x2_w, (float*)pwt2, KKDIM, KKDIM);
    k_transp<<<dim3(C_MID/32, C_MID/32), 256>>>(d2_w, (float*)pwtd, C_MID, C_MID);

    // fused: pts_local -> d1 -> d2 MMA -> g_lift, plus X0
    k_prep<<<NPTS/PB1, 256, PREP_SMEM>>>(rep_pt, pts, d1_w, d1_b,
                                         (const float*)pwtd, d2_b, cv_w, cv_b);

    // X1 = relu(X0 @ x1_w + x1_b):  M=16384, N=256, K=256
    k_mma<256, true, true><<<dim3(2, NPTS/128), 256, MMA_SMEM>>>(
        (const float*)pX0, (const float*)pwt1, x1_b, (float*)pX1, KKDIM);
    // X2 = X1 @ x2_w + x2_b
    k_mma<256, false, true><<<dim3(2, NPTS/128), 256, MMA_SMEM>>>(
        (const float*)pX1, (const float*)pwt2, x2_b, (float*)pX2, KKDIM);

    k_xform<<<NPTS/PB4, 192>>>(fts, dw_w, dw_b);

    // out = relu(dw @ pw_w^T):  M=16384, N=256, K=384  (pw_w already [N,K])
    k_mma<384, true, false><<<dim3(2, NPTS/128), 256, MMA_SMEM>>>(
        (const float*)pdw, pw_w, nullptr, out, C_OUT);

    k_stats<<<256, 256>>>(out);
    k_finstats<<<1, 256>>>(bn_g, bn_b);
    k_bn<<<(NPTS*C_OUT)/1024, 256>>>(out);
}

// round 14
// speedup vs baseline: 1.0014x; 1.0014x over previous
#include <cuda_runtime.h>
#include <cuda_bf16.h>
#include <cstdint>

#define NB    16
#define PP    1024
#define KNB   16
#define DIMS  3
#define C_IN  128
#define C_MID 64
#define C_OUT 256
#define DMUL  2
#define C_CAT 192
#define NPTS  (NB*PP)        // 16384
#define KKDIM 256            // K*K
#define EPSV  1e-5f

// ---------------- scratch ----------------
__device__ float g_lift[NPTS*KNB*C_MID];
__device__ float g_X0[NPTS*KKDIM];
__device__ float g_X1[NPTS*KKDIM];
__device__ float g_X2[NPTS*KKDIM];
__device__ float g_dw[NPTS*C_CAT*DMUL];
__device__ float g_wt1[KKDIM*KKDIM];         // x1_w transposed [N,K]
__device__ float g_wt2[KKDIM*KKDIM];
__device__ float g_wtd[C_MID*C_MID];         // d2_w transposed
__device__ double g_sum[C_OUT];
__device__ double g_sumsq[C_OUT];
__device__ float g_scale[C_OUT];
__device__ float g_shift[C_OUT];

// ---------------- K0 ----------------
__global__ void k_zero() {
    int t = threadIdx.x;
    if (t < C_OUT) { g_sum[t] = 0.0; g_sumsq[t] = 0.0; }
}

// ---------------- transpose: src[R][C] -> dst[C][R] ----------------
__global__ void k_transp(const float* __restrict__ src, float* __restrict__ dst,
                         int R, int C) {
    __shared__ float s[32][33];
    int bx = blockIdx.x, by = blockIdx.y;
    int tx = threadIdx.x & 31, ty = threadIdx.x >> 5;
    #pragma unroll
    for (int i = 0; i < 4; ++i) {
        int r = by * 32 + ty + i * 8;
        s[ty + i * 8][tx] = src[r * C + bx * 32 + tx];
    }
    __syncthreads();
    #pragma unroll
    for (int i = 0; i < 4; ++i) {
        int r = bx * 32 + ty + i * 8;
        dst[r * R + by * 32 + tx] = s[tx][ty + i * 8];
    }
}

__device__ __forceinline__ void mma16816(float* c, const uint32_t* a,
                                         uint32_t b0, uint32_t b1) {
    asm volatile(
        "mma.sync.aligned.m16n8k16.row.col.f32.bf16.bf16.f32 "
        "{%0,%1,%2,%3}, {%4,%5,%6,%7}, {%8,%9}, {%0,%1,%2,%3};"
        : "+f"(c[0]), "+f"(c[1]), "+f"(c[2]), "+f"(c[3])
        : "r"(a[0]), "r"(a[1]), "r"(a[2]), "r"(a[3]), "r"(b0), "r"(b1));
}

__device__ __forceinline__ void ldsm_x4(uint32_t& r0, uint32_t& r1,
                                        uint32_t& r2, uint32_t& r3, uint32_t addr) {
    asm volatile("ldmatrix.sync.aligned.m8n8.x4.shared.b16 {%0,%1,%2,%3}, [%4];"
                 : "=r"(r0), "=r"(r1), "=r"(r2), "=r"(r3) : "r"(addr));
}
__device__ __forceinline__ uint32_t smem_u32(const void* p) {
    return (uint32_t)__cvta_generic_to_shared(p);
}

__device__ __forceinline__ void split_bf16(float4 v, __nv_bfloat162& h01,
                                           __nv_bfloat162& h23,
                                           __nv_bfloat162& l01,
                                           __nv_bfloat162& l23) {
    h01 = __float22bfloat162_rn(make_float2(v.x, v.y));
    h23 = __float22bfloat162_rn(make_float2(v.z, v.w));
    float2 f01 = __bfloat1622float2(h01);
    float2 f23 = __bfloat1622float2(h23);
    l01 = __float22bfloat162_rn(make_float2(v.x - f01.x, v.y - f01.y));
    l23 = __float22bfloat162_rn(make_float2(v.z - f23.x, v.w - f23.y));
}

// ---------------- K1 fused: pts_local -> d1 MLP -> d2 MMA -> g_lift, + X0 ----------------
// 1 CTA = 8 points = 128 rows (one MMA tile). d2 GEMM done in-place via bf16x3 mma.
#define PB1 8
#define PSTR 72   // smem col stride (bf16 elems); 144 B rows: 16B-aligned, conflict-free
#define SPL_BYTES 1536                      // PB1*KNB*DIMS floats = 384*4
__global__ __launch_bounds__(256) void k_prep(
        const float* __restrict__ rep_pt, const float* __restrict__ pts,
        const float* __restrict__ d1_w, const float* __restrict__ d1_b,
        const float* __restrict__ d2wt, const float* __restrict__ d2_b,
        const float* __restrict__ cv_w, const float* __restrict__ cv_b) {
    extern __shared__ char smem[];
    float* s_pl = (float*)smem;                                        // 1536 B
    __nv_bfloat16* sA = (__nv_bfloat16*)(smem + SPL_BYTES);            // [2][128][PSTR]
    __nv_bfloat16* sB = (__nv_bfloat16*)(smem + SPL_BYTES + 2*128*PSTR*2); // [2][64][PSTR]
#define SA(pl, r, cc) sA[((pl)*128 + (r))*PSTR + (cc)]
#define SB(pl, r, cc) sB[((pl)*64 + (r))*PSTR + (cc)]

    const int t = threadIdx.x;
    const int pbase = blockIdx.x * PB1;
    const int wid = t >> 5, lid = t & 31;
    const int g = lid >> 2, tg = lid & 3;
    const int wm = wid & 3, wn = wid >> 2;

    for (int idx = t; idx < PB1*KNB*DIMS; idx += 256) {
        int p = idx / (KNB*DIMS);
        int rem = idx % (KNB*DIMS);
        int k = rem / DIMS, d = rem % DIMS;
        int gp = pbase + p;
        s_pl[idx] = pts[(gp*KNB + k)*DIMS + d] - rep_pt[gp*DIMS + d];
    }
    // stage d2wt [64][64] as bf16 hi/lo
    for (int idx = t * 4; idx < C_MID*C_MID; idx += 1024) {
        int row = idx >> 6, col = idx & 63;
        float4 v = *reinterpret_cast<const float4*>(&d2wt[idx]);
        __nv_bfloat162 h01, h23, l01, l23;
        split_bf16(v, h01, h23, l01, l23);
        *reinterpret_cast<__nv_bfloat162*>(&SB(0, row, col))     = h01;
        *reinterpret_cast<__nv_bfloat162*>(&SB(0, row, col + 2)) = h23;
        *reinterpret_cast<__nv_bfloat162*>(&SB(1, row, col))     = l01;
        *reinterpret_cast<__nv_bfloat162*>(&SB(1, row, col + 2)) = l23;
    }
    __syncthreads();

    // h = relu(pts_local @ d1_w + d1_b) -> sA hi/lo (2 cols x 16 rows per thread)
    {
        int c0 = (t & 31) * 2;
        int rg = t >> 5;                           // 0..7, 16 rows each
        float w00 = d1_w[0*C_MID + c0], w01 = d1_w[0*C_MID + c0 + 1];
        float w10 = d1_w[1*C_MID + c0], w11 = d1_w[1*C_MID + c0 + 1];
        float w20 = d1_w[2*C_MID + c0], w21 = d1_w[2*C_MID + c0 + 1];
        float b0 = d1_b[c0], b1 = d1_b[c0 + 1];
        #pragma unroll
        for (int r = 0; r < 16; ++r) {
            int row = rg * 16 + r;
            const float* pl = &s_pl[row * DIMS];
            float v0 = fmaxf(b0 + pl[0]*w00 + pl[1]*w10 + pl[2]*w20, 0.f);
            float v1 = fmaxf(b1 + pl[0]*w01 + pl[1]*w11 + pl[2]*w21, 0.f);
            __nv_bfloat162 h = __float22bfloat162_rn(make_float2(v0, v1));
            float2 hf = __bfloat1622float2(h);
            __nv_bfloat162 l = __float22bfloat162_rn(make_float2(v0 - hf.x, v1 - hf.y));
            *reinterpret_cast<__nv_bfloat162*>(&SA(0, row, c0)) = h;
            *reinterpret_cast<__nv_bfloat162*>(&SA(1, row, c0)) = l;
        }
    }
    __syncthreads();

    // d2 MMA: 128x64, K=64, bf16x3.  8 warps = 4m x 2n; warp tile 32 x 32.  ldmatrix frags.
    {
        float acc[2][4][4];
        #pragma unroll
        for (int mt = 0; mt < 2; ++mt)
            #pragma unroll
            for (int nt = 0; nt < 4; ++nt)
                #pragma unroll
                for (int i = 0; i < 4; ++i) acc[mt][nt][i] = 0.f;

        const int arow = ((lid >> 3) & 1) * 8 + (lid & 7);   // + mt*16 + wm*32
        const int acol = (lid >> 4) * 8;                      // + kb0
        const int brow = (lid >> 4) * 8 + (lid & 7);          // + nt*8 + wn*32
        const int bcol = ((lid >> 3) & 1) * 8;                // + kb0

        #pragma unroll
        for (int ks = 0; ks < 4; ++ks) {
            int kb0 = ks * 16;
            uint32_t ah[2][4], al[2][4];
            #pragma unroll
            for (int mt = 0; mt < 2; ++mt) {
                int r = wm * 32 + mt * 16 + arow;
                ldsm_x4(ah[mt][0], ah[mt][1], ah[mt][2], ah[mt][3],
                        smem_u32(&SA(0, r, kb0 + acol)));
                ldsm_x4(al[mt][0], al[mt][1], al[mt][2], al[mt][3],
                        smem_u32(&SA(1, r, kb0 + acol)));
            }
            #pragma unroll
            for (int ntp = 0; ntp < 2; ++ntp) {
                int nt = ntp * 2;
                int n = wn * 32 + nt * 8 + brow;
                uint32_t bh0, bh1, bh2, bh3, bl0, bl1, bl2, bl3;
                ldsm_x4(bh0, bh1, bh2, bh3, smem_u32(&SB(0, n, kb0 + bcol)));
                ldsm_x4(bl0, bl1, bl2, bl3, smem_u32(&SB(1, n, kb0 + bcol)));
                #pragma unroll
                for (int mt = 0; mt < 2; ++mt) {
                    mma16816(acc[mt][nt],     ah[mt], bh0, bh1);
                    mma16816(acc[mt][nt],     ah[mt], bl0, bl1);
                    mma16816(acc[mt][nt],     al[mt], bh0, bh1);
                    mma16816(acc[mt][nt + 1], ah[mt], bh2, bh3);
                    mma16816(acc[mt][nt + 1], ah[mt], bl2, bl3);
                    mma16816(acc[mt][nt + 1], al[mt], bh2, bh3);
                }
            }
        }
        // epilogue: relu(acc + d2_b) -> g_lift
        #pragma unroll
        for (int mt = 0; mt < 2; ++mt) {
            int row0 = wm * 32 + mt * 16 + g;
            #pragma unroll
            for (int nt = 0; nt < 4; ++nt) {
                int col = wn * 32 + nt * 8 + 2 * tg;
                float b0 = d2_b[col], b1 = d2_b[col + 1];
                float v0 = fmaxf(acc[mt][nt][0] + b0, 0.f);
                float v1 = fmaxf(acc[mt][nt][1] + b1, 0.f);
                float v2 = fmaxf(acc[mt][nt][2] + b0, 0.f);
                float v3 = fmaxf(acc[mt][nt][3] + b1, 0.f);
                *reinterpret_cast<float2*>(
                    &g_lift[(size_t)(pbase*KNB + row0)*C_MID + col]) = make_float2(v0, v1);
                *reinterpret_cast<float2*>(
                    &g_lift[(size_t)(pbase*KNB + row0 + 8)*C_MID + col]) = make_float2(v2, v3);
            }
        }
    }

    // X0 = relu(einsum('pkd,odk->po') + cv_b)  (reads only s_pl)
    {
        int o = t;
        float acc[PB1];
        float b = cv_b[o];
        #pragma unroll
        for (int p = 0; p < PB1; ++p) acc[p] = b;
        #pragma unroll
        for (int d = 0; d < DIMS; ++d)
            for (int k = 0; k < KNB; ++k) {
                float w = cv_w[o*(DIMS*KNB) + d*KNB + k];
                #pragma unroll
                for (int p = 0; p < PB1; ++p)
                    acc[p] += s_pl[(p*KNB + k)*DIMS + d] * w;
            }
        #pragma unroll
        for (int p = 0; p < PB1; ++p)
            g_X0[(size_t)(pbase + p)*KKDIM + o] = fmaxf(acc[p], 0.f);
    }
#undef SA
#undef SB
}

// ---------------- bf16x3 tensor-core GEMM v3: ldmatrix + double-buffered smem ----------------
// C[M, Nn] = act(A[M, KD] @ Bt[Nn, KD]^T (+bias)).  Block tile 128x128, BK=32.
#define SPAD 40                               // 80 B rows
#define PLANE (128 * SPAD)                    // elems per plane
#define STAGE (4 * PLANE)                     // Ah, Al, Bh, Bl
template<int KD, bool RELU, bool USE_BIAS>
__global__ __launch_bounds__(256) void k_mma(
        const float* __restrict__ A, const float* __restrict__ Bt,
        const float* __restrict__ bias, float* __restrict__ C, int Nn) {
    extern __shared__ char smem_raw[];
    __nv_bfloat16* smem = (__nv_bfloat16*)smem_raw;
    constexpr int KCH = KD / 32;

    const int t = threadIdx.x;
    const int wid = t >> 5, lid = t & 31;
    const int g = lid >> 2, tg = lid & 3;
    const int wm = wid & 3, wn = wid >> 2;
    const long rowBase = (long)blockIdx.y * 128;
    const int nBase = blockIdx.x * 128;

    const int ldrow = t >> 3, ldcol = (t & 7) * 4;   // 256 thr: 32 rows x 8 col-groups
    const int arow = ((lid >> 3) & 1) * 8 + (lid & 7);
    const int acol = (lid >> 4) * 8;
    const int brow = (lid >> 4) * 8 + (lid & 7);
    const int bcol = ((lid >> 3) & 1) * 8;

    float acc[2][8][4];
    #pragma unroll
    for (int mt = 0; mt < 2; ++mt)
        #pragma unroll
        for (int nt = 0; nt < 8; ++nt)
            #pragma unroll
            for (int i = 0; i < 4; ++i) acc[mt][nt][i] = 0.f;

    auto load_stage = [&](int ch, int st) {
        __nv_bfloat16* sAh = smem + st * STAGE;
        __nv_bfloat16* sAl = sAh + PLANE;
        __nv_bfloat16* sBh = sAh + 2 * PLANE;
        __nv_bfloat16* sBl = sAh + 3 * PLANE;
        #pragma unroll
        for (int i = 0; i < 4; ++i) {           // 128 rows x 32 cols, 4 passes
            int row = ldrow + i * 32;
            int col = ldcol;
            float4 va = *reinterpret_cast<const float4*>(
                &A[(rowBase + row) * KD + ch * 32 + col]);
            float4 vb = *reinterpret_cast<const float4*>(
                &Bt[(long)(nBase + row) * KD + ch * 32 + col]);
            __nv_bfloat162 h01, h23, l01, l23;
            split_bf16(va, h01, h23, l01, l23);
            int off = row * SPAD + col;
            *reinterpret_cast<__nv_bfloat162*>(&sAh[off])     = h01;
            *reinterpret_cast<__nv_bfloat162*>(&sAh[off + 2]) = h23;
            *reinterpret_cast<__nv_bfloat162*>(&sAl[off])     = l01;
            *reinterpret_cast<__nv_bfloat162*>(&sAl[off + 2]) = l23;
            split_bf16(vb, h01, h23, l01, l23);
            *reinterpret_cast<__nv_bfloat162*>(&sBh[off])     = h01;
            *reinterpret_cast<__nv_bfloat162*>(&sBh[off + 2]) = h23;
            *reinterpret_cast<__nv_bfloat162*>(&sBl[off])     = l01;
            *reinterpret_cast<__nv_bfloat162*>(&sBl[off + 2]) = l23;
        }
    };

    load_stage(0, 0);
    __syncthreads();

    for (int ch = 0; ch < KCH; ++ch) {
        int p = ch & 1;
        if (ch + 1 < KCH) load_stage(ch + 1, p ^ 1);

        __nv_bfloat16* sAh = smem + p * STAGE;
        __nv_bfloat16* sAl = sAh + PLANE;
        __nv_bfloat16* sBh = sAh + 2 * PLANE;
        __nv_bfloat16* sBl = sAh + 3 * PLANE;

        #pragma unroll
        for (int ks = 0; ks < 2; ++ks) {
            int kb0 = ks * 16;
            uint32_t ah[2][4], al[2][4];
            #pragma unroll
            for (int mt = 0; mt < 2; ++mt) {
                int r = wm * 32 + mt * 16 + arow;
                ldsm_x4(ah[mt][0], ah[mt][1], ah[mt][2], ah[mt][3],
                        smem_u32(&sAh[r * SPAD + kb0 + acol]));
                ldsm_x4(al[mt][0], al[mt][1], al[mt][2], al[mt][3],
                        smem_u32(&sAl[r * SPAD + kb0 + acol]));
            }
            #pragma unroll
            for (int ntp = 0; ntp < 4; ++ntp) {
                int nt = ntp * 2;
                int n = wn * 64 + nt * 8 + brow;
                uint32_t bh0, bh1, bh2, bh3, bl0, bl1, bl2, bl3;
                ldsm_x4(bh0, bh1, bh2, bh3, smem_u32(&sBh[n * SPAD + kb0 + bcol]));
                ldsm_x4(bl0, bl1, bl2, bl3, smem_u32(&sBl[n * SPAD + kb0 + bcol]));
                #pragma unroll
                for (int mt = 0; mt < 2; ++mt) {
                    mma16816(acc[mt][nt],     ah[mt], bh0, bh1);
                    mma16816(acc[mt][nt],     ah[mt], bl0, bl1);
                    mma16816(acc[mt][nt],     al[mt], bh0, bh1);
                    mma16816(acc[mt][nt + 1], ah[mt], bh2, bh3);
                    mma16816(acc[mt][nt + 1], ah[mt], bl2, bl3);
                    mma16816(acc[mt][nt + 1], al[mt], bh2, bh3);
                }
            }
        }
        __syncthreads();
    }

    #pragma unroll
    for (int mt = 0; mt < 2; ++mt) {
        long row0 = rowBase + wm * 32 + mt * 16 + g;
        #pragma unroll
        for (int nt = 0; nt < 8; ++nt) {
            int col = nBase + wn * 64 + nt * 8 + 2 * tg;
            float b0 = USE_BIAS ? bias[col]     : 0.f;
            float b1 = USE_BIAS ? bias[col + 1] : 0.f;
            float v0 = acc[mt][nt][0] + b0, v1 = acc[mt][nt][1] + b1;
            float v2 = acc[mt][nt][2] + b0, v3 = acc[mt][nt][3] + b1;
            if (RELU) {
                v0 = fmaxf(v0, 0.f); v1 = fmaxf(v1, 0.f);
                v2 = fmaxf(v2, 0.f); v3 = fmaxf(v3, 0.f);
            }
            *reinterpret_cast<float2*>(&C[row0 * Nn + col])       = make_float2(v0, v1);
            *reinterpret_cast<float2*>(&C[(row0 + 8) * Nn + col]) = make_float2(v2, v3);
        }
    }
}

// ---------------- K4: fts_X = X @ [lifted|fts], then depthwise conv -> g_dw ----------------
#define PB4 8
__global__ __launch_bounds__(192) void k_xform(
        const float* __restrict__ fts,
        const float* __restrict__ dw_w, const float* __restrict__ dw_b) {
    __shared__ __align__(16) float s_Xt[16][20];   // transposed X, padded rows
    const int t = threadIdx.x;                     // 0..191 = channel c
    const int pbase = blockIdx.x * PB4;
    const int c = t;
    float wreg[DMUL][KNB];
    float breg[DMUL];
    #pragma unroll
    for (int m = 0; m < DMUL; ++m) {
        int jj = c*DMUL + m;
        breg[m] = dw_b[jj];
        #pragma unroll
        for (int k = 0; k < KNB; ++k) wreg[m][k] = dw_w[jj*KNB + k];
    }
    for (int p = 0; p < PB4; ++p) {
        int gp = pbase + p;
        for (int idx = t; idx < KKDIM; idx += 192)     // s_Xt[j][k] = X[k][j]
            s_Xt[idx & 15][idx >> 4] = g_X2[(size_t)gp*KKDIM + idx];
        __syncthreads();
        float fX[KNB];
        #pragma unroll
        for (int k = 0; k < KNB; ++k) fX[k] = 0.f;
        #pragma unroll 4
        for (int j = 0; j < KNB; ++j) {
            float catv = (c < C_MID) ? g_lift[(size_t)(gp*KNB + j)*C_MID + c]
                                     : fts[(size_t)(gp*KNB + j)*C_IN + (c - C_MID)];
            #pragma unroll
            for (int q = 0; q < 4; ++q) {
                float4 xv = *reinterpret_cast<const float4*>(&s_Xt[j][q * 4]);
                fX[q*4+0] += xv.x * catv;
                fX[q*4+1] += xv.y * catv;
                fX[q*4+2] += xv.z * catv;
                fX[q*4+3] += xv.w * catv;
            }
        }
        #pragma unroll
        for (int m = 0; m < DMUL; ++m) {
            float acc = breg[m];
            #pragma unroll
            for (int k = 0; k < KNB; ++k)
                acc += fX[k] * wreg[m][k];
            g_dw[(size_t)gp*(C_CAT*DMUL) + c*DMUL + m] = acc;
        }
        __syncthreads();
    }
}

// ---------------- K5: per-channel sum / sumsq ----------------
__global__ void k_stats(const float* __restrict__ out) {
    const int c = threadIdx.x;
    const int rows_per = NPTS / gridDim.x;
    const int r0 = blockIdx.x * rows_per;
    double s = 0.0, s2 = 0.0;
    for (int r = 0; r < rows_per; ++r) {
        float v = out[(size_t)(r0 + r)*C_OUT + c];
        s += v; s2 += (double)v * v;
    }
    atomicAdd(&g_sum[c], s);
    atomicAdd(&g_sumsq[c], s2);
}

// ---------------- K5b ----------------
__global__ void k_finstats(const float* __restrict__ bn_g, const float* __restrict__ bn_b) {
    int c = threadIdx.x;
    double inv = 1.0 / (double)NPTS;
    double mean = g_sum[c] * inv;
    double var  = g_sumsq[c] * inv - mean*mean;
    float sc = bn_g[c] * rsqrtf((float)var + EPSV);
    g_scale[c] = sc;
    g_shift[c] = bn_b[c] - (float)mean * sc;
}

// ---------------- K6: apply BN (float4) ----------------
__global__ void k_bn(float* __restrict__ out) {
    int idx = (blockIdx.x * 256 + threadIdx.x) * 4;
    int c = idx & (C_OUT - 1);
    float4 v = *reinterpret_cast<float4*>(&out[idx]);
    v.x = v.x * g_scale[c]   + g_shift[c];
    v.y = v.y * g_scale[c+1] + g_shift[c+1];
    v.z = v.z * g_scale[c+2] + g_shift[c+2];
    v.w = v.w * g_scale[c+3] + g_shift[c+3];
    *reinterpret_cast<float4*>(&out[idx]) = v;
}

// ---------------- launch ----------------
extern "C" void kernel_launch(void* const* d_in, const int* in_sizes, int n_in,
                              void* d_out, int out_size) {
    const float* rep_pt = (const float*)d_in[0];
    const float* pts    = (const float*)d_in[1];
    const float* fts    = (const float*)d_in[2];
    const float* d1_w   = (const float*)d_in[3];
    const float* d1_b   = (const float*)d_in[4];
    const float* d2_w   = (const float*)d_in[5];
    const float* d2_b   = (const float*)d_in[6];
    const float* cv_w   = (const float*)d_in[7];
    const float* cv_b   = (const float*)d_in[8];
    const float* x1_w   = (const float*)d_in[9];
    const float* x1_b   = (const float*)d_in[10];
    const float* x2_w   = (const float*)d_in[11];
    const float* x2_b   = (const float*)d_in[12];
    const float* dw_w   = (const float*)d_in[13];
    const float* dw_b   = (const float*)d_in[14];
    const float* pw_w   = (const float*)d_in[15];
    const float* bn_g   = (const float*)d_in[16];
    const float* bn_b   = (const float*)d_in[17];
    float* out = (float*)d_out;

    void *pX0, *pX1, *pX2, *pdw, *pwt1, *pwt2, *pwtd;
    cudaGetSymbolAddress(&pX0,  g_X0);
    cudaGetSymbolAddress(&pX1,  g_X1);
    cudaGetSymbolAddress(&pX2,  g_X2);
    cudaGetSymbolAddress(&pdw,  g_dw);
    cudaGetSymbolAddress(&pwt1, g_wt1);
    cudaGetSymbolAddress(&pwt2, g_wt2);
    cudaGetSymbolAddress(&pwtd, g_wtd);

    constexpr int PREP_SMEM = SPL_BYTES + 2*128*PSTR*2 + 2*64*PSTR*2;  // 56832
    constexpr int MMA_SMEM  = 2 * STAGE * 2;                            // 81920 B
    cudaFuncSetAttribute(k_prep, cudaFuncAttributeMaxDynamicSharedMemorySize, PREP_SMEM);
    cudaFuncSetAttribute(k_mma<256, true,  true >,
                         cudaFuncAttributeMaxDynamicSharedMemorySize, MMA_SMEM);
    cudaFuncSetAttribute(k_mma<256, false, true >,
                         cudaFuncAttributeMaxDynamicSharedMemorySize, MMA_SMEM);
    cudaFuncSetAttribute(k_mma<384, true,  false>,
                         cudaFuncAttributeMaxDynamicSharedMemorySize, MMA_SMEM);

    k_zero<<<1, 256>>>();
    k_transp<<<dim3(KKDIM/32, KKDIM/32), 256>>>(x1_w, (float*)pwt1, KKDIM, KKDIM);
    k_transp<<<dim3(KKDIM/32, KKDIM/32), 256>>>(x2_w, (float*)pwt2, KKDIM, KKDIM);
    k_transp<<<dim3(C_MID/32, C_MID/32), 256>>>(d2_w, (float*)pwtd, C_MID, C_MID);

    // fused: pts_local -> d1 -> d2 MMA -> g_lift, plus X0
    k_prep<<<NPTS/PB1, 256, PREP_SMEM>>>(rep_pt, pts, d1_w, d1_b,
                                         (const float*)pwtd, d2_b, cv_w, cv_b);

    // X1 = relu(X0 @ x1_w + x1_b):  M=16384, N=256, K=256
    k_mma<256, true, true><<<dim3(2, NPTS/128), 256, MMA_SMEM>>>(
        (const float*)pX0, (const float*)pwt1, x1_b, (float*)pX1, KKDIM);
    // X2 = X1 @ x2_w + x2_b
    k_mma<256, false, true><<<dim3(2, NPTS/128), 256, MMA_SMEM>>>(
        (const float*)pX1, (const float*)pwt2, x2_b, (float*)pX2, KKDIM);

    k_xform<<<NPTS/PB4, 192>>>(fts, dw_w, dw_b);

    // out = relu(dw @ pw_w^T):  M=16384, N=256, K=384  (pw_w already [N,K])
    k_mma<384, true, false><<<dim3(2, NPTS/128), 256, MMA_SMEM>>>(
        (const float*)pdw, pw_w, nullptr, out, C_OUT);

    k_stats<<<256, 256>>>(out);
    k_finstats<<<1, 256>>>(bn_g, bn_b);
    k_bn<<<(NPTS*C_OUT)/1024, 256>>>(out);
}